// round 4
// baseline (speedup 1.0000x reference)
#include <cuda_runtime.h>
#include <cstdint>
#include <cstddef>

#define N_ATOMS 10000
#define N_PAIRS 250000
#define NP 128
#define NO 128

#define PXNEW_OFF ((size_t)0)
#define IX_OFF    ((size_t)N_ATOMS * 3 * NP)
#define DOT_OFF   (IX_OFF + (size_t)N_PAIRS * 3 * NP)

#define ATOMS_PB 8          // atoms per block
#define NBLK (N_ATOMS / ATOMS_PB)
#define CAP 128             // per-atom smem pair capacity (max seg ~55 expected)

// ---- device scratch (allocation-free; zero-initialized at load) ----
__device__ int g_count[N_ATOMS];     // invariant: zero at entry (k_scan restores)
__device__ int g_offset[N_ATOMS + 1];
__device__ int g_cursor[N_ATOMS];
__device__ int g_pairs[N_PAIRS];

// ---------------------------------------------------------------------------
__global__ void k_hist(const int4* __restrict__ ind2v) {
    int p = blockIdx.x * blockDim.x + threadIdx.x;
    if (p < N_PAIRS / 2) {
        int4 v = ind2v[p];
        atomicAdd(&g_count[v.x], 1);
        atomicAdd(&g_count[v.z], 1);
    }
}

__global__ void k_scan() {
    __shared__ int sb[1024];
    const int CH = 10;
    int t = threadIdx.x;
    int base = t * CH;
    int c[CH];
    int local = 0;
#pragma unroll
    for (int i = 0; i < CH; i++) {
        int idx = base + i;
        c[i] = (idx < N_ATOMS) ? g_count[idx] : 0;
        if (idx < N_ATOMS) g_count[idx] = 0;   // restore zero invariant
        local += c[i];
    }
    sb[t] = local;
    __syncthreads();
    for (int o = 1; o < 1024; o <<= 1) {
        int v = (t >= o) ? sb[t - o] : 0;
        __syncthreads();
        sb[t] += v;
        __syncthreads();
    }
    int run = sb[t] - local;
#pragma unroll
    for (int i = 0; i < CH; i++) {
        int idx = base + i;
        if (idx < N_ATOMS) {
            g_offset[idx] = run;
            g_cursor[idx] = run;
            run += c[i];
        }
    }
    if (t == 1023) g_offset[N_ATOMS] = sb[1023];
}

__global__ void k_scatter(const int4* __restrict__ ind2v) {
    int p = blockIdx.x * blockDim.x + threadIdx.x;
    if (p < N_PAIRS / 2) {
        int4 v = ind2v[p];
        int pos0 = atomicAdd(&g_cursor[v.x], 1);
        int pos1 = atomicAdd(&g_cursor[v.z], 1);
        g_pairs[pos0] = 2 * p;
        g_pairs[pos1] = 2 * p + 1;
    }
}

// ---------------------------------------------------------------------------
// k_main: block = 8 atoms, 256 threads = 8 warps.
// Phase 1: warp w owns atom (blk*8+w): rank-sort pair ids, prefetch j/diff,
//          compute ix (streamed), accumulate segment sum in registers -> s_fin.
// Phase 2: block GEMM (2 p-groups x 4 row-groups) with w_pp (L1-resident),
//          deterministic partial add, write px_new + dotted.
__global__ void __launch_bounds__(256, 4)
k_main(const int* __restrict__ ind2,
       const float* __restrict__ px,
       const float* __restrict__ i1,
       const float* __restrict__ diff,
       const float* __restrict__ wpp,
       float* __restrict__ out) {
    __shared__ int   s_pairs[ATOMS_PB][CAP];
    __shared__ int   s_j[ATOMS_PB][CAP];
    __shared__ float s_d[3][ATOMS_PB][CAP];
    __shared__ __align__(16) float s_fin[ATOMS_PB][3][NP];    // segment sums
    __shared__ __align__(16) float s_part[4][6][NP];          // pg1 GEMM partials

    const int blk = blockIdx.x;
    const int t = threadIdx.x;
    const int l = t & 31;
    const int w = t >> 5;            // warp id = local atom id
    const int q0 = 4 * l;

    const int a   = blk * ATOMS_PB + w;
    const int beg = g_offset[a];
    const int cnt0 = g_offset[a + 1] - beg;
    const int cnt  = cnt0 < CAP ? cnt0 : CAP;

    // ---- load + per-warp rank sort (deterministic order) ----
    for (int k = l; k < cnt; k += 32) s_pairs[w][k] = g_pairs[beg + k];
    __syncwarp();
    {
        int vv[4], rr[4], nh = 0;
        for (int k = l; k < cnt; k += 32) {
            int v = s_pairs[w][k];
            int r = 0;
            for (int m = 0; m < cnt; m++) r += (s_pairs[w][m] < v);
            vv[nh] = v; rr[nh] = r; nh++;
        }
        __syncwarp();
        for (int h = 0; h < nh; h++) s_pairs[w][rr[h]] = vv[h];
        __syncwarp();
    }

    // ---- prefetch j and diff (parallel gathers) ----
    for (int k = l; k < cnt; k += 32) {
        int pr = s_pairs[w][k];
        s_j[w][k]    = __ldg(&ind2[2 * pr + 1]);
        s_d[0][w][k] = __ldg(&diff[3 * pr + 0]);
        s_d[1][w][k] = __ldg(&diff[3 * pr + 1]);
        s_d[2][w][k] = __ldg(&diff[3 * pr + 2]);
    }
    __syncwarp();

    float* out_ix = out + IX_OFF;

    float4 acc0 = make_float4(0.f, 0.f, 0.f, 0.f);
    float4 acc1 = acc0, acc2 = acc0;

    // ---- pair loop: warp-serial, 2x unrolled (8 loads in flight) ----
    int k = 0;
    for (; k + 1 < cnt; k += 2) {
        int prA = s_pairs[w][k],     jA = s_j[w][k];
        int prB = s_pairs[w][k + 1], jB = s_j[w][k + 1];
        float dA0 = s_d[0][w][k],     dA1 = s_d[1][w][k],     dA2 = s_d[2][w][k];
        float dB0 = s_d[0][w][k + 1], dB1 = s_d[1][w][k + 1], dB2 = s_d[2][w][k + 1];

        float4 sA = __ldcs((const float4*)(i1 + (size_t)prA * NP + q0));
        float4 sB = __ldcs((const float4*)(i1 + (size_t)prB * NP + q0));
        const float* pjA = px + (size_t)jA * 3 * NP + q0;
        const float* pjB = px + (size_t)jB * 3 * NP + q0;
        float4 a0 = __ldg((const float4*)(pjA));
        float4 a1 = __ldg((const float4*)(pjA + NP));
        float4 a2 = __ldg((const float4*)(pjA + 2 * NP));
        float4 b0 = __ldg((const float4*)(pjB));
        float4 b1 = __ldg((const float4*)(pjB + NP));
        float4 b2 = __ldg((const float4*)(pjB + 2 * NP));

        float4 vA0, vA1, vA2, vB0, vB1, vB2;
        vA0.x = (a0.x + dA0) * sA.x; vA0.y = (a0.y + dA0) * sA.y;
        vA0.z = (a0.z + dA0) * sA.z; vA0.w = (a0.w + dA0) * sA.w;
        vA1.x = (a1.x + dA1) * sA.x; vA1.y = (a1.y + dA1) * sA.y;
        vA1.z = (a1.z + dA1) * sA.z; vA1.w = (a1.w + dA1) * sA.w;
        vA2.x = (a2.x + dA2) * sA.x; vA2.y = (a2.y + dA2) * sA.y;
        vA2.z = (a2.z + dA2) * sA.z; vA2.w = (a2.w + dA2) * sA.w;
        vB0.x = (b0.x + dB0) * sB.x; vB0.y = (b0.y + dB0) * sB.y;
        vB0.z = (b0.z + dB0) * sB.z; vB0.w = (b0.w + dB0) * sB.w;
        vB1.x = (b1.x + dB1) * sB.x; vB1.y = (b1.y + dB1) * sB.y;
        vB1.z = (b1.z + dB1) * sB.z; vB1.w = (b1.w + dB1) * sB.w;
        vB2.x = (b2.x + dB2) * sB.x; vB2.y = (b2.y + dB2) * sB.y;
        vB2.z = (b2.z + dB2) * sB.z; vB2.w = (b2.w + dB2) * sB.w;

        float* opA = out_ix + (size_t)prA * 3 * NP + q0;
        float* opB = out_ix + (size_t)prB * 3 * NP + q0;
        __stcs((float4*)(opA), vA0);
        __stcs((float4*)(opA + NP), vA1);
        __stcs((float4*)(opA + 2 * NP), vA2);
        __stcs((float4*)(opB), vB0);
        __stcs((float4*)(opB + NP), vB1);
        __stcs((float4*)(opB + 2 * NP), vB2);

        acc0.x += vA0.x + vB0.x; acc0.y += vA0.y + vB0.y;
        acc0.z += vA0.z + vB0.z; acc0.w += vA0.w + vB0.w;
        acc1.x += vA1.x + vB1.x; acc1.y += vA1.y + vB1.y;
        acc1.z += vA1.z + vB1.z; acc1.w += vA1.w + vB1.w;
        acc2.x += vA2.x + vB2.x; acc2.y += vA2.y + vB2.y;
        acc2.z += vA2.z + vB2.z; acc2.w += vA2.w + vB2.w;
    }
    for (; k < cnt0; k++) {
        int pr, j;
        float d0, d1, d2;
        if (k < CAP) {
            pr = s_pairs[w][k]; j = s_j[w][k];
            d0 = s_d[0][w][k]; d1 = s_d[1][w][k]; d2 = s_d[2][w][k];
        } else {   // overflow fallback (unreachable for this input)
            pr = g_pairs[beg + k]; j = ind2[2 * pr + 1];
            d0 = diff[3 * pr]; d1 = diff[3 * pr + 1]; d2 = diff[3 * pr + 2];
        }
        float4 s = __ldcs((const float4*)(i1 + (size_t)pr * NP + q0));
        const float* pj = px + (size_t)j * 3 * NP + q0;
        float4 p0 = __ldg((const float4*)(pj));
        float4 p1 = __ldg((const float4*)(pj + NP));
        float4 p2 = __ldg((const float4*)(pj + 2 * NP));

        float4 v0, v1, v2;
        v0.x = (p0.x + d0) * s.x; v0.y = (p0.y + d0) * s.y;
        v0.z = (p0.z + d0) * s.z; v0.w = (p0.w + d0) * s.w;
        v1.x = (p1.x + d1) * s.x; v1.y = (p1.y + d1) * s.y;
        v1.z = (p1.z + d1) * s.z; v1.w = (p1.w + d1) * s.w;
        v2.x = (p2.x + d2) * s.x; v2.y = (p2.y + d2) * s.y;
        v2.z = (p2.z + d2) * s.z; v2.w = (p2.w + d2) * s.w;

        float* op = out_ix + (size_t)pr * 3 * NP + q0;
        __stcs((float4*)(op), v0);
        __stcs((float4*)(op + NP), v1);
        __stcs((float4*)(op + 2 * NP), v2);

        acc0.x += v0.x; acc0.y += v0.y; acc0.z += v0.z; acc0.w += v0.w;
        acc1.x += v1.x; acc1.y += v1.y; acc1.z += v1.z; acc1.w += v1.w;
        acc2.x += v2.x; acc2.y += v2.y; acc2.z += v2.z; acc2.w += v2.w;
    }

    // segment sums -> smem (warp-private, no reduction needed)
    *(float4*)&s_fin[w][0][q0] = acc0;
    *(float4*)&s_fin[w][1][q0] = acc1;
    *(float4*)&s_fin[w][2][q0] = acc2;
    __syncthreads();

    // ---- GEMM phase: 24 rows (= 8 atoms x 3) x 128 cols ----
    // warp split: pg = w>>2 (p-range 64), rg = w&3 (rows [rg*6, rg*6+6) = atoms 2rg,2rg+1)
    const int pg = w >> 2;
    const int rg = w & 3;
    const int atom0 = 2 * rg;

    float4 g[6];
#pragma unroll
    for (int r = 0; r < 6; r++) g[r] = make_float4(0.f, 0.f, 0.f, 0.f);

    const int pbeg = pg * 64;
#pragma unroll 4
    for (int pp = 0; pp < 64; pp++) {
        int p = pbeg + pp;
        float4 wv = *(const float4*)&wpp[(size_t)p * NO + q0];
        float f0 = s_fin[atom0][0][p];
        float f1 = s_fin[atom0][1][p];
        float f2 = s_fin[atom0][2][p];
        float f3 = s_fin[atom0 + 1][0][p];
        float f4 = s_fin[atom0 + 1][1][p];
        float f5 = s_fin[atom0 + 1][2][p];
        g[0].x += f0 * wv.x; g[0].y += f0 * wv.y; g[0].z += f0 * wv.z; g[0].w += f0 * wv.w;
        g[1].x += f1 * wv.x; g[1].y += f1 * wv.y; g[1].z += f1 * wv.z; g[1].w += f1 * wv.w;
        g[2].x += f2 * wv.x; g[2].y += f2 * wv.y; g[2].z += f2 * wv.z; g[2].w += f2 * wv.w;
        g[3].x += f3 * wv.x; g[3].y += f3 * wv.y; g[3].z += f3 * wv.z; g[3].w += f3 * wv.w;
        g[4].x += f4 * wv.x; g[4].y += f4 * wv.y; g[4].z += f4 * wv.z; g[4].w += f4 * wv.w;
        g[5].x += f5 * wv.x; g[5].y += f5 * wv.y; g[5].z += f5 * wv.z; g[5].w += f5 * wv.w;
    }

    if (pg == 1) {
#pragma unroll
        for (int r = 0; r < 6; r++) *(float4*)&s_part[rg][r][q0] = g[r];
    }
    __syncthreads();

    if (pg == 0) {
        // deterministic final add: pg0 + pg1
#pragma unroll
        for (int r = 0; r < 6; r++) {
            float4 p1 = *(const float4*)&s_part[rg][r][q0];
            g[r].x += p1.x; g[r].y += p1.y; g[r].z += p1.z; g[r].w += p1.w;
        }
        // write px_new (6 rows = 2 atoms x 3)
        float* opx = out + PXNEW_OFF;
#pragma unroll
        for (int r = 0; r < 6; r++) {
            int row = (blk * ATOMS_PB + atom0) * 3 + r;   // atom0*3 + r spans both atoms
            *(float4*)&opx[(size_t)row * NP + q0] = g[r];
        }
        // dotted for the 2 atoms
#pragma unroll
        for (int al = 0; al < 2; al++) {
            float4 a0 = g[3 * al], a1 = g[3 * al + 1], a2 = g[3 * al + 2];
            float4 d;
            d.x = a0.x * a0.x + a1.x * a1.x + a2.x * a2.x;
            d.y = a0.y * a0.y + a1.y * a1.y + a2.y * a2.y;
            d.z = a0.z * a0.z + a1.z * a1.z + a2.z * a2.z;
            d.w = a0.w * a0.w + a1.w * a1.w + a2.w * a2.w;
            int atom = blk * ATOMS_PB + atom0 + al;
            *(float4*)&out[DOT_OFF + (size_t)atom * NO + q0] = d;
        }
    }
}

// ---------------------------------------------------------------------------
extern "C" void kernel_launch(void* const* d_in, const int* in_sizes, int n_in,
                              void* d_out, int out_size) {
    const int*   ind2 = (const int*)d_in[0];
    const float* px   = (const float*)d_in[1];
    const float* i1   = (const float*)d_in[2];
    const float* diff = (const float*)d_in[3];
    const float* wpp  = (const float*)d_in[4];
    float* out = (float*)d_out;

    k_hist<<<(N_PAIRS / 2 + 255) / 256, 256>>>((const int4*)ind2);
    k_scan<<<1, 1024>>>();
    k_scatter<<<(N_PAIRS / 2 + 255) / 256, 256>>>((const int4*)ind2);
    k_main<<<NBLK, 256>>>(ind2, px, i1, diff, wpp, out);
}